// round 1
// baseline (speedup 1.0000x reference)
#include <cuda_runtime.h>
#include <math.h>

// Problem dims
#define BB     8
#define TT     512
#define EE     64
#define HH     512
#define VV     32000
#define G3     1536        // 3*HH
#define MM     4096        // B*T
#define NCH    4096        // B*H channels for the scan
#define CHUNK  16
#define NCHUNK 32          // T / CHUNK

// Scratch (static device globals — runtime allocation is forbidden)
__device__ float g_buf[MM * G3];        // pre-pool activations (reused layer1/layer2) ~25 MB
__device__ float h1_buf[MM * HH];       // layer1 output, [t*B+b, h]
__device__ float h2_buf[MM * HH];       // layer2 output, [b*T+t, h]
__device__ float F_buf[NCHUNK * NCH];
__device__ float Gc_buf[NCHUNK * NCH];
__device__ float c0_buf[NCHUNK * NCH];

__device__ __forceinline__ float sigmoidf_(float x) {
    return 1.0f / (1.0f + expf(-x));
}

// ---------------------------------------------------------------------------
// GEMM1: g_buf[m, n] = act( sum_k emb[tok(m), k] * W1[k, n] + b1[n] )
// m = t*B + b, tok(m) = inputs[b*T + t]. K = 64 (single tile).
// Block tile: 64 (m) x 64 (n), 256 threads, 4x4 micro-tile per thread.
// ---------------------------------------------------------------------------
__global__ __launch_bounds__(256) void gemm1_kernel(
    const int* __restrict__ inputs, const float* __restrict__ emb,
    const float* __restrict__ W1, const float* __restrict__ b1)
{
    __shared__ float Xs[64 * 65];
    __shared__ float Ws[64 * 64];
    __shared__ int   toks[64];

    const int tid = threadIdx.x;
    const int m0 = blockIdx.y * 64;
    const int n0 = blockIdx.x * 64;

    if (tid < 64) {
        int m = m0 + tid;
        int b = m & 7;
        int t = m >> 3;
        toks[tid] = inputs[b * TT + t];
    }
    __syncthreads();

    #pragma unroll
    for (int i = 0; i < 16; i++) {
        int lin = tid + i * 256;          // 0..4095
        int row = lin >> 6, k = lin & 63;
        Xs[row * 65 + k] = emb[toks[row] * EE + k];
    }
    #pragma unroll
    for (int i = 0; i < 16; i++) {
        int lin = tid + i * 256;
        int k = lin >> 6, col = lin & 63;
        Ws[k * 64 + col] = W1[k * G3 + n0 + col];
    }
    __syncthreads();

    const int tx = tid & 15, ty = tid >> 4;
    float acc[4][4] = {};
    #pragma unroll
    for (int k = 0; k < 64; k++) {
        float a[4], w[4];
        #pragma unroll
        for (int i = 0; i < 4; i++) a[i] = Xs[(ty * 4 + i) * 65 + k];
        #pragma unroll
        for (int j = 0; j < 4; j++) w[j] = Ws[k * 64 + tx * 4 + j];
        #pragma unroll
        for (int i = 0; i < 4; i++)
            #pragma unroll
            for (int j = 0; j < 4; j++)
                acc[i][j] = fmaf(a[i], w[j], acc[i][j]);
    }

    #pragma unroll
    for (int i = 0; i < 4; i++) {
        int m = m0 + ty * 4 + i;
        #pragma unroll
        for (int j = 0; j < 4; j++) {
            int n = n0 + tx * 4 + j;
            float v = acc[i][j] + b1[n];
            v = (n < HH) ? tanhf(v) : sigmoidf_(v);
            g_buf[m * G3 + n] = v;
        }
    }
}

// ---------------------------------------------------------------------------
// fo-pool scan, 3 phases. Recurrence c_t = f_t*c_{t-1} + (1-f_t)*z_t is affine:
// over a chunk, c_out = F*c_in + G with F = prod f, G = (result with c_in = 0).
// channel ch = b*H + h; g_buf layout [(t*B+b)*G3 + {h, H+h, 2H+h}].
// Loads are coalesced over h (consecutive lanes -> consecutive addresses).
// ---------------------------------------------------------------------------
__global__ __launch_bounds__(256) void scan_phaseA_kernel()
{
    const int ch = blockIdx.x * 256 + threadIdx.x;   // 0..4095
    const int chunk = blockIdx.y;                    // 0..31
    const int b = ch >> 9, h = ch & 511;
    const int t0 = chunk * CHUNK;
    float c = 0.0f, F = 1.0f;
    #pragma unroll
    for (int i = 0; i < CHUNK; i++) {
        int base = ((t0 + i) * BB + b) * G3 + h;
        float z = g_buf[base];
        float f = g_buf[base + HH];
        c = f * c + (1.0f - f) * z;
        F *= f;
    }
    F_buf[chunk * NCH + ch]  = F;
    Gc_buf[chunk * NCH + ch] = c;
}

__global__ __launch_bounds__(256) void scan_phaseB_kernel()
{
    const int ch = blockIdx.x * 256 + threadIdx.x;
    float c = 0.0f;
    #pragma unroll
    for (int j = 0; j < NCHUNK; j++) {
        c0_buf[j * NCH + ch] = c;                    // c at chunk start
        float F = F_buf[j * NCH + ch];
        float G = Gc_buf[j * NCH + ch];
        c = F * c + G;
    }
}

// layer==0: write h1_buf[(t*B+b)*H + h]   (feeds GEMM2, row = t*B+b)
// layer==1: write h2_buf[(b*T+t)*H + h]   (feeds projection, row = b*T+t)
__global__ __launch_bounds__(256) void scan_phaseC_kernel(int layer)
{
    const int ch = blockIdx.x * 256 + threadIdx.x;
    const int chunk = blockIdx.y;
    const int b = ch >> 9, h = ch & 511;
    const int t0 = chunk * CHUNK;
    float c = c0_buf[chunk * NCH + ch];
    #pragma unroll
    for (int i = 0; i < CHUNK; i++) {
        int t = t0 + i;
        int base = (t * BB + b) * G3 + h;
        float z = g_buf[base];
        float f = g_buf[base + HH];
        float o = g_buf[base + 2 * HH];
        c = f * c + (1.0f - f) * z;
        float val = o * c;
        if (layer == 0) h1_buf[(t * BB + b) * HH + h] = val;
        else            h2_buf[(b * TT + t) * HH + h] = val;
    }
}

// ---------------------------------------------------------------------------
// Shared tiled SIMT GEMM: 128x128 block tile, BK=8, 256 threads, 8x8 micro.
// ACT=1: A = h1_buf, C = g_buf (N=1536), epilogue = bias + tanh/sigmoid.
// ACT=0: A = h2_buf, C = outp  (N=32000), epilogue = bias only.
// K = 512 always; M, N, K all divisible by tile dims -> no bounds checks.
// ---------------------------------------------------------------------------
template<int NN, int ACT>
__global__ __launch_bounds__(256) void gemm128_kernel(
    const float* __restrict__ Bm, const float* __restrict__ bias,
    float* __restrict__ outp)
{
    const float* __restrict__ A = ACT ? h1_buf : h2_buf;
    float* __restrict__ C = ACT ? g_buf : outp;
    const int K = 512;

    __shared__ float As[8 * 128];
    __shared__ float Bs[8 * 128];

    const int tid = threadIdx.x;
    const int m0 = blockIdx.y * 128;
    const int n0 = blockIdx.x * 128;

    const int aRow = tid >> 1;
    const int aK   = (tid & 1) * 4;
    const int bK   = tid >> 5;
    const int bCol = (tid & 31) * 4;

    const int tx = tid & 15, ty = tid >> 4;

    float acc[8][8] = {};

    for (int k0 = 0; k0 < K; k0 += 8) {
        float4 av = *(const float4*)&A[(m0 + aRow) * K + k0 + aK];
        float4 bv = *(const float4*)&Bm[(size_t)(k0 + bK) * NN + n0 + bCol];
        __syncthreads();
        As[(aK + 0) * 128 + aRow] = av.x;
        As[(aK + 1) * 128 + aRow] = av.y;
        As[(aK + 2) * 128 + aRow] = av.z;
        As[(aK + 3) * 128 + aRow] = av.w;
        *(float4*)&Bs[bK * 128 + bCol] = bv;
        __syncthreads();

        #pragma unroll
        for (int k = 0; k < 8; k++) {
            float4 a0 = *(const float4*)&As[k * 128 + ty * 8];
            float4 a1 = *(const float4*)&As[k * 128 + ty * 8 + 4];
            float4 b0 = *(const float4*)&Bs[k * 128 + tx * 8];
            float4 b1 = *(const float4*)&Bs[k * 128 + tx * 8 + 4];
            float ar[8] = {a0.x, a0.y, a0.z, a0.w, a1.x, a1.y, a1.z, a1.w};
            float br[8] = {b0.x, b0.y, b0.z, b0.w, b1.x, b1.y, b1.z, b1.w};
            #pragma unroll
            for (int i = 0; i < 8; i++)
                #pragma unroll
                for (int j = 0; j < 8; j++)
                    acc[i][j] = fmaf(ar[i], br[j], acc[i][j]);
        }
    }

    #pragma unroll
    for (int i = 0; i < 8; i++) {
        int m = m0 + ty * 8 + i;
        #pragma unroll
        for (int jj = 0; jj < 2; jj++) {
            int n = n0 + tx * 8 + jj * 4;
            float4 v;
            float vv[4];
            #pragma unroll
            for (int j = 0; j < 4; j++) {
                float x = acc[i][jj * 4 + j] + bias[n + j];
                if (ACT) x = ((n + j) < HH) ? tanhf(x) : sigmoidf_(x);
                vv[j] = x;
            }
            v.x = vv[0]; v.y = vv[1]; v.z = vv[2]; v.w = vv[3];
            *(float4*)&C[(size_t)m * NN + n] = v;
        }
    }
}

// ---------------------------------------------------------------------------
// Launch
// ---------------------------------------------------------------------------
extern "C" void kernel_launch(void* const* d_in, const int* in_sizes, int n_in,
                              void* d_out, int out_size)
{
    const int*   inputs = (const int*)d_in[0];
    const float* emb    = (const float*)d_in[1];
    const float* W1     = (const float*)d_in[2];
    const float* b1     = (const float*)d_in[3];
    const float* W2     = (const float*)d_in[4];
    const float* b2     = (const float*)d_in[5];
    const float* Wp     = (const float*)d_in[6];
    const float* bp     = (const float*)d_in[7];
    float* out = (float*)d_out;

    // Layer 1: embed + GEMM1 + activations -> g_buf
    gemm1_kernel<<<dim3(G3 / 64, MM / 64), 256>>>(inputs, emb, W1, b1);

    // Layer 1 fo-pool -> h1_buf [t*B+b, h]
    scan_phaseA_kernel<<<dim3(NCH / 256, NCHUNK), 256>>>();
    scan_phaseB_kernel<<<NCH / 256, 256>>>();
    scan_phaseC_kernel<<<dim3(NCH / 256, NCHUNK), 256>>>(0);

    // Layer 2 GEMM + activations -> g_buf (reused)
    gemm128_kernel<G3, 1><<<dim3(G3 / 128, MM / 128), 256>>>(W2, b2, nullptr);

    // Layer 2 fo-pool -> h2_buf [b*T+t, h]
    scan_phaseA_kernel<<<dim3(NCH / 256, NCHUNK), 256>>>();
    scan_phaseB_kernel<<<NCH / 256, 256>>>();
    scan_phaseC_kernel<<<dim3(NCH / 256, NCHUNK), 256>>>(1);

    // Projection: [4096, 512] x [512, 32000] + bp -> out [B,T,V]
    gemm128_kernel<VV, 0><<<dim3(VV / 128, MM / 128), 256>>>(Wp, bp, out);
}

// round 3
// speedup vs baseline: 1.9730x; 1.9730x over previous
#include <cuda_runtime.h>
#include <cuda_bf16.h>
#include <math.h>
#include <stdint.h>

// ---------------- dims ----------------
#define BB     8
#define TT     512
#define EE     64
#define HH     512
#define VV     32000
#define G3     1536
#define MM     4096        // B*T
#define KK     512
#define NCH    4096
#define CHUNK  16
#define NCHUNK 32

// ---------------- scratch (static device globals) ----------------
__device__ float g_buf[MM * G3];
__device__ float h1_buf[MM * HH];
__device__ float h2_buf[MM * HH];
__device__ float F_buf[NCHUNK * NCH];
__device__ float Gc_buf[NCHUNK * NCH];
__device__ float c0_buf[NCHUNK * NCH];

__device__ __nv_bfloat16 Ahi_buf[MM * KK];
__device__ __nv_bfloat16 Alo_buf[MM * KK];
__device__ __nv_bfloat16 B2hi_buf[G3 * KK];
__device__ __nv_bfloat16 B2lo_buf[G3 * KK];
__device__ __nv_bfloat16 Bphi_buf[(size_t)VV * KK];
__device__ __nv_bfloat16 Bplo_buf[(size_t)VV * KK];

__device__ __forceinline__ float sigmoidf_(float x) {
    return 1.0f / (1.0f + expf(-x));
}

__device__ __forceinline__ uint32_t smem_u32(const void* p) {
    uint32_t a;
    asm("{ .reg .u64 t; cvta.to.shared.u64 t, %1; cvt.u32.u64 %0, t; }" : "=r"(a) : "l"(p));
    return a;
}
__device__ __forceinline__ void cp_async16(uint32_t s, const void* g) {
    asm volatile("cp.async.cg.shared.global [%0], [%1], 16;" :: "r"(s), "l"(g));
}
__device__ __forceinline__ void cp_commit() {
    asm volatile("cp.async.commit_group;");
}
template<int N>
__device__ __forceinline__ void cp_wait() {
    asm volatile("cp.async.wait_group %0;" :: "n"(N));
}
__device__ __forceinline__ void ldm_x4(uint32_t& r0, uint32_t& r1, uint32_t& r2, uint32_t& r3,
                                       uint32_t addr) {
    asm volatile("ldmatrix.sync.aligned.m8n8.x4.shared.b16 {%0,%1,%2,%3}, [%4];"
                 : "=r"(r0), "=r"(r1), "=r"(r2), "=r"(r3) : "r"(addr));
}
__device__ __forceinline__ void mma_bf16(float& c0, float& c1, float& c2, float& c3,
                                         uint32_t a0, uint32_t a1, uint32_t a2, uint32_t a3,
                                         uint32_t b0, uint32_t b1) {
    asm volatile("mma.sync.aligned.m16n8k16.row.col.f32.bf16.bf16.f32 "
                 "{%0,%1,%2,%3}, {%4,%5,%6,%7}, {%8,%9}, {%0,%1,%2,%3};"
                 : "+f"(c0), "+f"(c1), "+f"(c2), "+f"(c3)
                 : "r"(a0), "r"(a1), "r"(a2), "r"(a3), "r"(b0), "r"(b1));
}

// ---------------------------------------------------------------------------
// GEMM1: embed-gather fused small GEMM, K=64
// ---------------------------------------------------------------------------
__global__ __launch_bounds__(256) void gemm1_kernel(
    const int* __restrict__ inputs, const float* __restrict__ emb,
    const float* __restrict__ W1, const float* __restrict__ b1)
{
    __shared__ float Xs[64 * 65];
    __shared__ float Ws[64 * 64];
    __shared__ int   toks[64];

    const int tid = threadIdx.x;
    const int m0 = blockIdx.y * 64;
    const int n0 = blockIdx.x * 64;

    if (tid < 64) {
        int m = m0 + tid;
        int b = m & 7;
        int t = m >> 3;
        toks[tid] = inputs[b * TT + t];
    }
    __syncthreads();

    #pragma unroll
    for (int i = 0; i < 16; i++) {
        int lin = tid + i * 256;
        int row = lin >> 6, k = lin & 63;
        Xs[row * 65 + k] = emb[toks[row] * EE + k];
    }
    #pragma unroll
    for (int i = 0; i < 16; i++) {
        int lin = tid + i * 256;
        int k = lin >> 6, col = lin & 63;
        Ws[k * 64 + col] = W1[k * G3 + n0 + col];
    }
    __syncthreads();

    const int tx = tid & 15, ty = tid >> 4;
    float acc[4][4] = {};
    #pragma unroll
    for (int k = 0; k < 64; k++) {
        float a[4], w[4];
        #pragma unroll
        for (int i = 0; i < 4; i++) a[i] = Xs[(ty * 4 + i) * 65 + k];
        #pragma unroll
        for (int j = 0; j < 4; j++) w[j] = Ws[k * 64 + tx * 4 + j];
        #pragma unroll
        for (int i = 0; i < 4; i++)
            #pragma unroll
            for (int j = 0; j < 4; j++)
                acc[i][j] = fmaf(a[i], w[j], acc[i][j]);
    }

    #pragma unroll
    for (int i = 0; i < 4; i++) {
        int m = m0 + ty * 4 + i;
        #pragma unroll
        for (int j = 0; j < 4; j++) {
            int n = n0 + tx * 4 + j;
            float v = acc[i][j] + b1[n];
            v = (n < HH) ? tanhf(v) : sigmoidf_(v);
            g_buf[m * G3 + n] = v;
        }
    }
}

// ---------------------------------------------------------------------------
// fo-pool scan, 3 phases (affine chunked scan)
// ---------------------------------------------------------------------------
__global__ __launch_bounds__(256) void scan_phaseA_kernel()
{
    const int ch = blockIdx.x * 256 + threadIdx.x;
    const int chunk = blockIdx.y;
    const int b = ch >> 9, h = ch & 511;
    const int t0 = chunk * CHUNK;
    float c = 0.0f, F = 1.0f;
    #pragma unroll
    for (int i = 0; i < CHUNK; i++) {
        int base = ((t0 + i) * BB + b) * G3 + h;
        float z = g_buf[base];
        float f = g_buf[base + HH];
        c = f * c + (1.0f - f) * z;
        F *= f;
    }
    F_buf[chunk * NCH + ch]  = F;
    Gc_buf[chunk * NCH + ch] = c;
}

__global__ __launch_bounds__(256) void scan_phaseB_kernel()
{
    const int ch = blockIdx.x * 256 + threadIdx.x;
    float c = 0.0f;
    #pragma unroll
    for (int j = 0; j < NCHUNK; j++) {
        c0_buf[j * NCH + ch] = c;
        float F = F_buf[j * NCH + ch];
        float G = Gc_buf[j * NCH + ch];
        c = F * c + G;
    }
}

__global__ __launch_bounds__(256) void scan_phaseC_kernel(int layer)
{
    const int ch = blockIdx.x * 256 + threadIdx.x;
    const int chunk = blockIdx.y;
    const int b = ch >> 9, h = ch & 511;
    const int t0 = chunk * CHUNK;
    float c = c0_buf[chunk * NCH + ch];
    #pragma unroll
    for (int i = 0; i < CHUNK; i++) {
        int t = t0 + i;
        int base = (t * BB + b) * G3 + h;
        float z = g_buf[base];
        float f = g_buf[base + HH];
        float o = g_buf[base + 2 * HH];
        c = f * c + (1.0f - f) * z;
        float val = o * c;
        if (layer == 0) h1_buf[(t * BB + b) * HH + h] = val;
        else            h2_buf[(b * TT + t) * HH + h] = val;
    }
}

// ---------------------------------------------------------------------------
// fp32 -> bf16 hi/lo split (elementwise)
// ---------------------------------------------------------------------------
__global__ __launch_bounds__(256) void convert_split_kernel(
    const float* __restrict__ in, __nv_bfloat16* __restrict__ hi,
    __nv_bfloat16* __restrict__ lo)
{
    int i = blockIdx.x * 256 + threadIdx.x;
    float x = in[i];
    __nv_bfloat16 h = __float2bfloat16_rn(x);
    float r = x - __bfloat162float(h);
    hi[i] = h;
    lo[i] = __float2bfloat16_rn(r);
}

// ---------------------------------------------------------------------------
// W [K=512, N] row-major  ->  B [N, K=512] bf16 hi/lo (transpose + split)
// ---------------------------------------------------------------------------
__global__ __launch_bounds__(256) void transpose_split_kernel(
    const float* __restrict__ W, int N,
    __nv_bfloat16* __restrict__ Bhi, __nv_bfloat16* __restrict__ Blo)
{
    __shared__ float ts[32][33];
    const int n0 = blockIdx.x * 32;
    const int k0 = blockIdx.y * 32;
    const int tx = threadIdx.x, ty = threadIdx.y;

    #pragma unroll
    for (int i = 0; i < 4; i++)
        ts[ty + i * 8][tx] = W[(size_t)(k0 + ty + i * 8) * N + n0 + tx];
    __syncthreads();
    #pragma unroll
    for (int i = 0; i < 4; i++) {
        float x = ts[tx][ty + i * 8];
        __nv_bfloat16 h = __float2bfloat16_rn(x);
        float r = x - __bfloat162float(h);
        size_t o = (size_t)(n0 + ty + i * 8) * KK + k0 + tx;
        Bhi[o] = h;
        Blo[o] = __float2bfloat16_rn(r);
    }
}

// ---------------------------------------------------------------------------
// HMMA bf16 split GEMM: C[M,N] = A[M,512] * B[N,512]^T  (+bias, opt act)
// 3 passes (AhiBhi + AhiBlo + AloBhi) folded into one 48-chunk K loop.
// CTA 128x128, 8 warps (2m x 4n), warp 64x32, mma m16n8k16.
// SMEM rows padded to 40 bf16 (80B): ldmatrix conflict-free (20r mod 32 distinct).
// Double-buffered cp.async, K-chunk 32.
// ---------------------------------------------------------------------------
#define LDS_STRIDE 40   // bf16 elems per smem row (32 data + 8 pad)

template<int NGLOB, int ACT>
__global__ __launch_bounds__(256, 2) void tgemm_kernel(
    const __nv_bfloat16* __restrict__ Ahi, const __nv_bfloat16* __restrict__ Alo,
    const __nv_bfloat16* __restrict__ Bhi, const __nv_bfloat16* __restrict__ Blo,
    const float* __restrict__ bias, float* __restrict__ C)
{
    __shared__ __nv_bfloat16 As[2][128 * LDS_STRIDE];
    __shared__ __nv_bfloat16 Bs[2][128 * LDS_STRIDE];

    const int tid  = threadIdx.x;
    const int wid  = tid >> 5;
    const int lane = tid & 31;
    const int m0 = blockIdx.y * 128;
    const int n0 = blockIdx.x * 128;
    const int wm = (wid & 1) * 64;     // warp m offset
    const int wn = (wid >> 1) * 32;    // warp n offset

    const uint32_t sA[2] = { smem_u32(As[0]), smem_u32(As[1]) };
    const uint32_t sB[2] = { smem_u32(Bs[0]), smem_u32(Bs[1]) };

    // cp.async mapping: 512 16B-chunks per 128x32 tile; thread does 2 for A, 2 for B.
    const int ldRow = tid >> 2;          // 0..63 (+64 on second iter)
    const int ldG   = tid & 3;           // 16B chunk within row (8 bf16)

    float acc[4][4][4];
    #pragma unroll
    for (int i = 0; i < 4; i++)
        #pragma unroll
        for (int j = 0; j < 4; j++)
            #pragma unroll
            for (int r = 0; r < 4; r++) acc[i][j][r] = 0.0f;

    auto issue_loads = [&](int c, int s) {
        const __nv_bfloat16* Ap = (c >= 32) ? Alo : Ahi;
        const __nv_bfloat16* Bp = (c >= 16 && c < 32) ? Blo : Bhi;
        const int k0 = (c & 15) * 32;
        #pragma unroll
        for (int it = 0; it < 2; it++) {
            int row = ldRow + it * 64;
            uint32_t soff = (uint32_t)(row * LDS_STRIDE + ldG * 8) * 2;
            cp_async16(sA[s] + soff, Ap + (size_t)(m0 + row) * KK + k0 + ldG * 8);
            cp_async16(sB[s] + soff, Bp + (size_t)(n0 + row) * KK + k0 + ldG * 8);
        }
        cp_commit();
    };

    issue_loads(0, 0);

    for (int c = 0; c < 48; c++) {
        const int s = c & 1;
        if (c + 1 < 48) {
            issue_loads(c + 1, s ^ 1);
            cp_wait<1>();
        } else {
            cp_wait<0>();
        }
        __syncthreads();

        #pragma unroll
        for (int ks = 0; ks < 2; ks++) {
            const int kb = ks * 32;  // byte offset of k16 step within 64B row data

            // A fragments: 4 m16 tiles
            uint32_t af[4][4];
            #pragma unroll
            for (int mt = 0; mt < 4; mt++) {
                int row = wm + mt * 16 + (lane & 15);
                uint32_t addr = sA[s] + (uint32_t)(row * LDS_STRIDE) * 2 + kb
                                + ((lane >> 4) * 16);
                ldm_x4(af[mt][0], af[mt][1], af[mt][2], af[mt][3], addr);
            }
            // B fragments: 2 x ldmatrix.x4, each covering two n8 tiles
            uint32_t bf[4][2];
            #pragma unroll
            for (int nt2 = 0; nt2 < 2; nt2++) {
                int row = wn + nt2 * 16 + (lane & 7) + ((lane >> 4) & 1) * 8;
                uint32_t addr = sB[s] + (uint32_t)(row * LDS_STRIDE) * 2 + kb
                                + (((lane >> 3) & 1) * 16);
                uint32_t r0, r1, r2, r3;
                ldm_x4(r0, r1, r2, r3, addr);
                bf[nt2 * 2 + 0][0] = r0; bf[nt2 * 2 + 0][1] = r1;
                bf[nt2 * 2 + 1][0] = r2; bf[nt2 * 2 + 1][1] = r3;
            }

            #pragma unroll
            for (int mt = 0; mt < 4; mt++)
                #pragma unroll
                for (int nt = 0; nt < 4; nt++)
                    mma_bf16(acc[mt][nt][0], acc[mt][nt][1], acc[mt][nt][2], acc[mt][nt][3],
                             af[mt][0], af[mt][1], af[mt][2], af[mt][3],
                             bf[nt][0], bf[nt][1]);
        }
        __syncthreads();
    }

    // Epilogue: bias (+ optional activation), float2 stores.
    const int g = lane >> 2;
    const int cpair = (lane & 3) * 2;
    #pragma unroll
    for (int nt = 0; nt < 4; nt++) {
        int n = n0 + wn + nt * 8 + cpair;
        float bv0 = __ldg(bias + n);
        float bv1 = __ldg(bias + n + 1);
        #pragma unroll
        for (int mt = 0; mt < 4; mt++) {
            #pragma unroll
            for (int half = 0; half < 2; half++) {
                int m = m0 + wm + mt * 16 + g + half * 8;
                float x0 = acc[mt][nt][half * 2 + 0] + bv0;
                float x1 = acc[mt][nt][half * 2 + 1] + bv1;
                if (ACT) {
                    x0 = (n < HH) ? tanhf(x0) : sigmoidf_(x0);
                    x1 = (n + 1 < HH) ? tanhf(x1) : sigmoidf_(x1);
                }
                float2 v = make_float2(x0, x1);
                *(float2*)(C + (size_t)m * NGLOB + n) = v;
            }
        }
    }
}

// ---------------------------------------------------------------------------
// Launch
// ---------------------------------------------------------------------------
extern "C" void kernel_launch(void* const* d_in, const int* in_sizes, int n_in,
                              void* d_out, int out_size)
{
    const int*   inputs = (const int*)d_in[0];
    const float* emb    = (const float*)d_in[1];
    const float* W1     = (const float*)d_in[2];
    const float* b1     = (const float*)d_in[3];
    const float* W2     = (const float*)d_in[4];
    const float* b2     = (const float*)d_in[5];
    const float* Wp     = (const float*)d_in[6];
    const float* bp     = (const float*)d_in[7];
    float* out = (float*)d_out;

    float *g_h1, *g_h2, *g_gbuf;
    __nv_bfloat16 *g_Ahi, *g_Alo, *g_B2hi, *g_B2lo, *g_Bphi, *g_Bplo;
    cudaGetSymbolAddress((void**)&g_h1,   h1_buf);
    cudaGetSymbolAddress((void**)&g_h2,   h2_buf);
    cudaGetSymbolAddress((void**)&g_gbuf, g_buf);
    cudaGetSymbolAddress((void**)&g_Ahi,  Ahi_buf);
    cudaGetSymbolAddress((void**)&g_Alo,  Alo_buf);
    cudaGetSymbolAddress((void**)&g_B2hi, B2hi_buf);
    cudaGetSymbolAddress((void**)&g_B2lo, B2lo_buf);
    cudaGetSymbolAddress((void**)&g_Bphi, Bphi_buf);
    cudaGetSymbolAddress((void**)&g_Bplo, Bplo_buf);

    // Layer 1: embed + GEMM1 + activations -> g_buf
    gemm1_kernel<<<dim3(G3 / 64, MM / 64), 256>>>(inputs, emb, W1, b1);

    // Layer 1 fo-pool -> h1_buf
    scan_phaseA_kernel<<<dim3(NCH / 256, NCHUNK), 256>>>();
    scan_phaseB_kernel<<<NCH / 256, 256>>>();
    scan_phaseC_kernel<<<dim3(NCH / 256, NCHUNK), 256>>>(0);

    // Layer 2: HMMA split-bf16 GEMM -> g_buf with activations
    convert_split_kernel<<<(MM * HH) / 256, 256>>>(g_h1, g_Ahi, g_Alo);
    transpose_split_kernel<<<dim3(G3 / 32, KK / 32), dim3(32, 8)>>>(W2, G3, g_B2hi, g_B2lo);
    tgemm_kernel<G3, 1><<<dim3(G3 / 128, MM / 128), 256>>>(
        g_Ahi, g_Alo, g_B2hi, g_B2lo, b2, g_gbuf);

    // Layer 2 fo-pool -> h2_buf
    scan_phaseA_kernel<<<dim3(NCH / 256, NCHUNK), 256>>>();
    scan_phaseB_kernel<<<NCH / 256, 256>>>();
    scan_phaseC_kernel<<<dim3(NCH / 256, NCHUNK), 256>>>(1);

    // Projection: HMMA split-bf16 GEMM -> out
    convert_split_kernel<<<(MM * HH) / 256, 256>>>(g_h2, g_Ahi, g_Alo);
    transpose_split_kernel<<<dim3(VV / 32, KK / 32), dim3(32, 8)>>>(Wp, VV, g_Bphi, g_Bplo);
    tgemm_kernel<VV, 0><<<dim3(VV / 128, MM / 128), 256>>>(
        g_Ahi, g_Alo, g_Bphi, g_Bplo, bp, out);
}

// round 5
// speedup vs baseline: 2.5068x; 1.2705x over previous
#include <cuda_runtime.h>
#include <cuda_bf16.h>
#include <math.h>
#include <stdint.h>

// ---------------- dims ----------------
#define BB     8
#define TT     512
#define EE     64
#define HH     512
#define VV     32000
#define G3     1536
#define MM     4096        // B*T
#define KK     512
#define NCH    4096
#define CHUNK  16
#define NCHUNK 32

// ---------------- scratch (static device globals) ----------------
__device__ float g_buf[MM * G3];
__device__ float F_buf[NCHUNK * NCH];
__device__ float Gc_buf[NCHUNK * NCH];
__device__ float c0_buf[NCHUNK * NCH];

__device__ __nv_bfloat16 Ahi_buf[MM * KK];
__device__ __nv_bfloat16 Alo_buf[MM * KK];
__device__ __nv_bfloat16 B2hi_buf[G3 * KK];
__device__ __nv_bfloat16 B2lo_buf[G3 * KK];
__device__ __nv_bfloat16 Bphi_buf[(size_t)VV * KK];
__device__ __nv_bfloat16 Bplo_buf[(size_t)VV * KK];

__device__ __forceinline__ float sigmoidf_(float x) {
    return 1.0f / (1.0f + expf(-x));
}

__device__ __forceinline__ uint32_t smem_u32(const void* p) {
    uint32_t a;
    asm("{ .reg .u64 t; cvta.to.shared.u64 t, %1; cvt.u32.u64 %0, t; }" : "=r"(a) : "l"(p));
    return a;
}
__device__ __forceinline__ void cp_async16(uint32_t s, const void* g) {
    asm volatile("cp.async.cg.shared.global [%0], [%1], 16;" :: "r"(s), "l"(g));
}
__device__ __forceinline__ void cp_commit() {
    asm volatile("cp.async.commit_group;");
}
template<int N>
__device__ __forceinline__ void cp_wait() {
    asm volatile("cp.async.wait_group %0;" :: "n"(N));
}
__device__ __forceinline__ void ldm_x4(uint32_t& r0, uint32_t& r1, uint32_t& r2, uint32_t& r3,
                                       uint32_t addr) {
    asm volatile("ldmatrix.sync.aligned.m8n8.x4.shared.b16 {%0,%1,%2,%3}, [%4];"
                 : "=r"(r0), "=r"(r1), "=r"(r2), "=r"(r3) : "r"(addr));
}
__device__ __forceinline__ void mma_bf16(float& c0, float& c1, float& c2, float& c3,
                                         uint32_t a0, uint32_t a1, uint32_t a2, uint32_t a3,
                                         uint32_t b0, uint32_t b1) {
    asm volatile("mma.sync.aligned.m16n8k16.row.col.f32.bf16.bf16.f32 "
                 "{%0,%1,%2,%3}, {%4,%5,%6,%7}, {%8,%9}, {%0,%1,%2,%3};"
                 : "+f"(c0), "+f"(c1), "+f"(c2), "+f"(c3)
                 : "r"(a0), "r"(a1), "r"(a2), "r"(a3), "r"(b0), "r"(b1));
}

// ---------------------------------------------------------------------------
// GEMM1: embed-gather fused small GEMM, K=64
// ---------------------------------------------------------------------------
__global__ __launch_bounds__(256) void gemm1_kernel(
    const int* __restrict__ inputs, const float* __restrict__ emb,
    const float* __restrict__ W1, const float* __restrict__ b1)
{
    __shared__ float Xs[64 * 65];
    __shared__ float Ws[64 * 64];
    __shared__ int   toks[64];

    const int tid = threadIdx.x;
    const int m0 = blockIdx.y * 64;
    const int n0 = blockIdx.x * 64;

    if (tid < 64) {
        int m = m0 + tid;
        int b = m & 7;
        int t = m >> 3;
        toks[tid] = inputs[b * TT + t];
    }
    __syncthreads();

    #pragma unroll
    for (int i = 0; i < 16; i++) {
        int lin = tid + i * 256;
        int row = lin >> 6, k = lin & 63;
        Xs[row * 65 + k] = emb[toks[row] * EE + k];
    }
    #pragma unroll
    for (int i = 0; i < 16; i++) {
        int lin = tid + i * 256;
        int k = lin >> 6, col = lin & 63;
        Ws[k * 64 + col] = W1[k * G3 + n0 + col];
    }
    __syncthreads();

    const int tx = tid & 15, ty = tid >> 4;
    float acc[4][4] = {};
    #pragma unroll
    for (int k = 0; k < 64; k++) {
        float a[4], w[4];
        #pragma unroll
        for (int i = 0; i < 4; i++) a[i] = Xs[(ty * 4 + i) * 65 + k];
        #pragma unroll
        for (int j = 0; j < 4; j++) w[j] = Ws[k * 64 + tx * 4 + j];
        #pragma unroll
        for (int i = 0; i < 4; i++)
            #pragma unroll
            for (int j = 0; j < 4; j++)
                acc[i][j] = fmaf(a[i], w[j], acc[i][j]);
    }

    #pragma unroll
    for (int i = 0; i < 4; i++) {
        int m = m0 + ty * 4 + i;
        #pragma unroll
        for (int j = 0; j < 4; j++) {
            int n = n0 + tx * 4 + j;
            float v = acc[i][j] + b1[n];
            v = (n < HH) ? tanhf(v) : sigmoidf_(v);
            g_buf[m * G3 + n] = v;
        }
    }
}

// ---------------------------------------------------------------------------
// fo-pool scan, 3 phases (affine chunked scan).
// Phase C writes the bf16 hi/lo split of o*c directly into Ahi/Alo
// (row = t*B+b for layer 0, row = b*T+t for layer 1).
// ---------------------------------------------------------------------------
__global__ __launch_bounds__(256) void scan_phaseA_kernel()
{
    const int ch = blockIdx.x * 256 + threadIdx.x;
    const int chunk = blockIdx.y;
    const int b = ch >> 9, h = ch & 511;
    const int t0 = chunk * CHUNK;
    float c = 0.0f, F = 1.0f;
    #pragma unroll
    for (int i = 0; i < CHUNK; i++) {
        int base = ((t0 + i) * BB + b) * G3 + h;
        float z = g_buf[base];
        float f = g_buf[base + HH];
        c = f * c + (1.0f - f) * z;
        F *= f;
    }
    F_buf[chunk * NCH + ch]  = F;
    Gc_buf[chunk * NCH + ch] = c;
}

__global__ __launch_bounds__(256) void scan_phaseB_kernel()
{
    const int ch = blockIdx.x * 256 + threadIdx.x;
    float c = 0.0f;
    #pragma unroll
    for (int j = 0; j < NCHUNK; j++) {
        c0_buf[j * NCH + ch] = c;
        float F = F_buf[j * NCH + ch];
        float G = Gc_buf[j * NCH + ch];
        c = F * c + G;
    }
}

__global__ __launch_bounds__(256) void scan_phaseC_kernel(int layer)
{
    const int ch = blockIdx.x * 256 + threadIdx.x;
    const int chunk = blockIdx.y;
    const int b = ch >> 9, h = ch & 511;
    const int t0 = chunk * CHUNK;
    float c = c0_buf[chunk * NCH + ch];
    #pragma unroll
    for (int i = 0; i < CHUNK; i++) {
        int t = t0 + i;
        int base = (t * BB + b) * G3 + h;
        float z = g_buf[base];
        float f = g_buf[base + HH];
        float o = g_buf[base + 2 * HH];
        c = f * c + (1.0f - f) * z;
        float val = o * c;
        int idx = (layer == 0) ? ((t * BB + b) * HH + h) : ((b * TT + t) * HH + h);
        __nv_bfloat16 hi = __float2bfloat16_rn(val);
        float r = val - __bfloat162float(hi);
        Ahi_buf[idx] = hi;
        Alo_buf[idx] = __float2bfloat16_rn(r);
    }
}

// ---------------------------------------------------------------------------
// W [K=512, N] row-major  ->  B [N, K=512] bf16 hi/lo (transpose + split)
// ---------------------------------------------------------------------------
__global__ __launch_bounds__(256) void transpose_split_kernel(
    const float* __restrict__ W, int N,
    __nv_bfloat16* __restrict__ Bhi, __nv_bfloat16* __restrict__ Blo)
{
    __shared__ float ts[32][33];
    const int n0 = blockIdx.x * 32;
    const int k0 = blockIdx.y * 32;
    const int tx = threadIdx.x, ty = threadIdx.y;

    #pragma unroll
    for (int i = 0; i < 4; i++)
        ts[ty + i * 8][tx] = W[(size_t)(k0 + ty + i * 8) * N + n0 + tx];
    __syncthreads();
    #pragma unroll
    for (int i = 0; i < 4; i++) {
        float x = ts[tx][ty + i * 8];
        __nv_bfloat16 h = __float2bfloat16_rn(x);
        float r = x - __bfloat162float(h);
        size_t o = (size_t)(n0 + ty + i * 8) * KK + k0 + tx;
        Bhi[o] = h;
        Blo[o] = __float2bfloat16_rn(r);
    }
}

// ---------------------------------------------------------------------------
// HMMA bf16 split GEMM: C[M,N] = A[M,512] * B[N,512]^T  (+bias, opt act)
// 3 passes (AhiBhi + AhiBlo + AloBhi) folded into one 48-chunk K loop.
// CTA 128x128, 4 warps (2m x 2n), warp 64x64, mma m16n8k16.
// SMEM rows padded to 40 bf16 (80B): ldmatrix conflict-free.
// 3-stage cp.async pipeline, 1 barrier per chunk.
// Stage indices: compute stage = c % 3, prefetch target = (c+2) % 3.
// ---------------------------------------------------------------------------
#define LDS_STRIDE 40          // bf16 elems per smem row (32 data + 8 pad)
#define STAGE_BYTES 20480      // (128 A rows + 128 B rows) * 80 B
#define TG_SMEM (3 * STAGE_BYTES)

template<int NGLOB, int ACT>
__global__ __launch_bounds__(128, 2) void tgemm_kernel(
    const __nv_bfloat16* __restrict__ Ahi, const __nv_bfloat16* __restrict__ Alo,
    const __nv_bfloat16* __restrict__ Bhi, const __nv_bfloat16* __restrict__ Blo,
    const float* __restrict__ bias, float* __restrict__ C)
{
    extern __shared__ __nv_bfloat16 dsm[];
    const uint32_t sbase = smem_u32(dsm);

    const int tid  = threadIdx.x;
    const int wid  = tid >> 5;
    const int lane = tid & 31;
    const int m0 = blockIdx.y * 128;
    const int n0 = blockIdx.x * 128;
    const int wm = (wid & 1) * 64;
    const int wn = (wid >> 1) * 64;

    const int ldRow = tid >> 2;          // 0..31
    const int ldG   = tid & 3;           // 16B chunk within row

    float acc[4][8][4] = {};

    auto issue_loads = [&](int c, int s) {
        const __nv_bfloat16* Ap = (c >= 32) ? Alo : Ahi;
        const __nv_bfloat16* Bp = (c >= 16 && c < 32) ? Blo : Bhi;
        const int k0 = (c & 15) * 32;
        const uint32_t sA = sbase + s * STAGE_BYTES;
        const uint32_t sB = sA + 10240;
        #pragma unroll
        for (int it = 0; it < 4; it++) {
            int row = ldRow + it * 32;
            uint32_t soff = (uint32_t)(row * LDS_STRIDE + ldG * 8) * 2;
            cp_async16(sA + soff, Ap + (size_t)(m0 + row) * KK + k0 + ldG * 8);
            cp_async16(sB + soff, Bp + (size_t)(n0 + row) * KK + k0 + ldG * 8);
        }
        cp_commit();
    };

    issue_loads(0, 0);
    issue_loads(1, 1);

    int s  = 0;   // compute stage = c % 3
    int sp = 2;   // prefetch stage = (c+2) % 3
    for (int c = 0; c < 48; c++) {
        if (c + 1 < 48) cp_wait<1>(); else cp_wait<0>();
        __syncthreads();
        if (c + 2 < 48) issue_loads(c + 2, sp);

        const uint32_t sA = sbase + s * STAGE_BYTES;
        const uint32_t sB = sA + 10240;

        #pragma unroll
        for (int ks = 0; ks < 2; ks++) {
            const int kb = ks * 32;

            uint32_t af[4][4];
            #pragma unroll
            for (int mt = 0; mt < 4; mt++) {
                int row = wm + mt * 16 + (lane & 15);
                uint32_t addr = sA + (uint32_t)(row * LDS_STRIDE) * 2 + kb
                                + ((lane >> 4) * 16);
                ldm_x4(af[mt][0], af[mt][1], af[mt][2], af[mt][3], addr);
            }
            uint32_t bf[8][2];
            #pragma unroll
            for (int nt2 = 0; nt2 < 4; nt2++) {
                int row = wn + nt2 * 16 + (lane & 7) + ((lane >> 4) & 1) * 8;
                uint32_t addr = sB + (uint32_t)(row * LDS_STRIDE) * 2 + kb
                                + (((lane >> 3) & 1) * 16);
                uint32_t r0, r1, r2, r3;
                ldm_x4(r0, r1, r2, r3, addr);
                bf[nt2 * 2 + 0][0] = r0; bf[nt2 * 2 + 0][1] = r1;
                bf[nt2 * 2 + 1][0] = r2; bf[nt2 * 2 + 1][1] = r3;
            }

            #pragma unroll
            for (int mt = 0; mt < 4; mt++)
                #pragma unroll
                for (int nt = 0; nt < 8; nt++)
                    mma_bf16(acc[mt][nt][0], acc[mt][nt][1], acc[mt][nt][2], acc[mt][nt][3],
                             af[mt][0], af[mt][1], af[mt][2], af[mt][3],
                             bf[nt][0], bf[nt][1]);
        }
        s  = (s  == 2) ? 0 : s  + 1;
        sp = (sp == 2) ? 0 : sp + 1;
    }

    // Epilogue: bias (+ optional activation), float2 stores.
    const int g = lane >> 2;
    const int cpair = (lane & 3) * 2;
    #pragma unroll
    for (int nt = 0; nt < 8; nt++) {
        int n = n0 + wn + nt * 8 + cpair;
        float bv0 = __ldg(bias + n);
        float bv1 = __ldg(bias + n + 1);
        #pragma unroll
        for (int mt = 0; mt < 4; mt++) {
            #pragma unroll
            for (int half = 0; half < 2; half++) {
                int m = m0 + wm + mt * 16 + g + half * 8;
                float x0 = acc[mt][nt][half * 2 + 0] + bv0;
                float x1 = acc[mt][nt][half * 2 + 1] + bv1;
                if (ACT) {
                    x0 = (n < HH) ? tanhf(x0) : sigmoidf_(x0);
                    x1 = (n + 1 < HH) ? tanhf(x1) : sigmoidf_(x1);
                }
                float2 v = make_float2(x0, x1);
                *(float2*)(C + (size_t)m * NGLOB + n) = v;
            }
        }
    }
}

// ---------------------------------------------------------------------------
// Launch
// ---------------------------------------------------------------------------
extern "C" void kernel_launch(void* const* d_in, const int* in_sizes, int n_in,
                              void* d_out, int out_size)
{
    const int*   inputs = (const int*)d_in[0];
    const float* emb    = (const float*)d_in[1];
    const float* W1     = (const float*)d_in[2];
    const float* b1     = (const float*)d_in[3];
    const float* W2     = (const float*)d_in[4];
    const float* b2     = (const float*)d_in[5];
    const float* Wp     = (const float*)d_in[6];
    const float* bp     = (const float*)d_in[7];
    float* out = (float*)d_out;

    cudaFuncSetAttribute(tgemm_kernel<G3, 1>,
                         cudaFuncAttributeMaxDynamicSharedMemorySize, TG_SMEM);
    cudaFuncSetAttribute(tgemm_kernel<VV, 0>,
                         cudaFuncAttributeMaxDynamicSharedMemorySize, TG_SMEM);

    float* g_gbuf;
    __nv_bfloat16 *g_Ahi, *g_Alo, *g_B2hi, *g_B2lo, *g_Bphi, *g_Bplo;
    cudaGetSymbolAddress((void**)&g_gbuf, g_buf);
    cudaGetSymbolAddress((void**)&g_Ahi,  Ahi_buf);
    cudaGetSymbolAddress((void**)&g_Alo,  Alo_buf);
    cudaGetSymbolAddress((void**)&g_B2hi, B2hi_buf);
    cudaGetSymbolAddress((void**)&g_B2lo, B2lo_buf);
    cudaGetSymbolAddress((void**)&g_Bphi, Bphi_buf);
    cudaGetSymbolAddress((void**)&g_Bplo, Bplo_buf);

    // Weight prep (independent of activations)
    transpose_split_kernel<<<dim3(G3 / 32, KK / 32), dim3(32, 8)>>>(W2, G3, g_B2hi, g_B2lo);
    transpose_split_kernel<<<dim3(VV / 32, KK / 32), dim3(32, 8)>>>(Wp, VV, g_Bphi, g_Bplo);

    // Layer 1: embed + GEMM1 + activations -> g_buf
    gemm1_kernel<<<dim3(G3 / 64, MM / 64), 256>>>(inputs, emb, W1, b1);

    // Layer 1 fo-pool -> Ahi/Alo (bf16 split), rows t*B+b
    scan_phaseA_kernel<<<dim3(NCH / 256, NCHUNK), 256>>>();
    scan_phaseB_kernel<<<NCH / 256, 256>>>();
    scan_phaseC_kernel<<<dim3(NCH / 256, NCHUNK), 256>>>(0);

    // Layer 2: HMMA split-bf16 GEMM -> g_buf with activations
    tgemm_kernel<G3, 1><<<dim3(G3 / 128, MM / 128), 128, TG_SMEM>>>(
        g_Ahi, g_Alo, g_B2hi, g_B2lo, b2, g_gbuf);

    // Layer 2 fo-pool -> Ahi/Alo (bf16 split), rows b*T+t
    scan_phaseA_kernel<<<dim3(NCH / 256, NCHUNK), 256>>>();
    scan_phaseB_kernel<<<NCH / 256, 256>>>();
    scan_phaseC_kernel<<<dim3(NCH / 256, NCHUNK), 256>>>(1);

    // Projection: HMMA split-bf16 GEMM -> out
    tgemm_kernel<VV, 0><<<dim3(VV / 128, MM / 128), 128, TG_SMEM>>>(
        g_Ahi, g_Alo, g_Bphi, g_Bplo, bp, out);
}

// round 6
// speedup vs baseline: 2.5871x; 1.0320x over previous
#include <cuda_runtime.h>
#include <cuda_bf16.h>
#include <math.h>
#include <stdint.h>

// ---------------- dims ----------------
#define BB     8
#define TT     512
#define EE     64
#define HH     512
#define VV     32000
#define G3     1536
#define MM     4096        // B*T
#define KK     512
#define NCH    4096
#define CHUNK  16
#define NCHUNK 32

// ---------------- scratch (static device globals) ----------------
__device__ float g_buf[MM * G3];
__device__ float F_buf[NCHUNK * NCH];
__device__ float Gc_buf[NCHUNK * NCH];
__device__ float c0_buf[NCHUNK * NCH];

__device__ __nv_bfloat16 Ahi_buf[MM * KK];
__device__ __nv_bfloat16 Alo_buf[MM * KK];
__device__ __nv_bfloat16 B2hi_buf[G3 * KK];
__device__ __nv_bfloat16 B2lo_buf[G3 * KK];
__device__ __nv_bfloat16 Bphi_buf[(size_t)VV * KK];
__device__ __nv_bfloat16 Bplo_buf[(size_t)VV * KK];

__device__ __forceinline__ float sigmoidf_(float x) {
    return 1.0f / (1.0f + expf(-x));
}

__device__ __forceinline__ uint32_t smem_u32(const void* p) {
    uint32_t a;
    asm("{ .reg .u64 t; cvta.to.shared.u64 t, %1; cvt.u32.u64 %0, t; }" : "=r"(a) : "l"(p));
    return a;
}
__device__ __forceinline__ void cp_async16(uint32_t s, const void* g) {
    asm volatile("cp.async.cg.shared.global [%0], [%1], 16;" :: "r"(s), "l"(g));
}
__device__ __forceinline__ void cp_commit() {
    asm volatile("cp.async.commit_group;");
}
template<int N>
__device__ __forceinline__ void cp_wait() {
    asm volatile("cp.async.wait_group %0;" :: "n"(N));
}
__device__ __forceinline__ void ldm_x4(uint32_t& r0, uint32_t& r1, uint32_t& r2, uint32_t& r3,
                                       uint32_t addr) {
    asm volatile("ldmatrix.sync.aligned.m8n8.x4.shared.b16 {%0,%1,%2,%3}, [%4];"
                 : "=r"(r0), "=r"(r1), "=r"(r2), "=r"(r3) : "r"(addr));
}
__device__ __forceinline__ void mma_bf16(float& c0, float& c1, float& c2, float& c3,
                                         uint32_t a0, uint32_t a1, uint32_t a2, uint32_t a3,
                                         uint32_t b0, uint32_t b1) {
    asm volatile("mma.sync.aligned.m16n8k16.row.col.f32.bf16.bf16.f32 "
                 "{%0,%1,%2,%3}, {%4,%5,%6,%7}, {%8,%9}, {%0,%1,%2,%3};"
                 : "+f"(c0), "+f"(c1), "+f"(c2), "+f"(c3)
                 : "r"(a0), "r"(a1), "r"(a2), "r"(a3), "r"(b0), "r"(b1));
}

// ---------------------------------------------------------------------------
// GEMM1: embed-gather fused small GEMM, K=64
// ---------------------------------------------------------------------------
__global__ __launch_bounds__(256) void gemm1_kernel(
    const int* __restrict__ inputs, const float* __restrict__ emb,
    const float* __restrict__ W1, const float* __restrict__ b1)
{
    __shared__ float Xs[64 * 65];
    __shared__ float Ws[64 * 64];
    __shared__ int   toks[64];

    const int tid = threadIdx.x;
    const int m0 = blockIdx.y * 64;
    const int n0 = blockIdx.x * 64;

    if (tid < 64) {
        int m = m0 + tid;
        int b = m & 7;
        int t = m >> 3;
        toks[tid] = inputs[b * TT + t];
    }
    __syncthreads();

    #pragma unroll
    for (int i = 0; i < 16; i++) {
        int lin = tid + i * 256;
        int row = lin >> 6, k = lin & 63;
        Xs[row * 65 + k] = emb[toks[row] * EE + k];
    }
    #pragma unroll
    for (int i = 0; i < 16; i++) {
        int lin = tid + i * 256;
        int k = lin >> 6, col = lin & 63;
        Ws[k * 64 + col] = W1[k * G3 + n0 + col];
    }
    __syncthreads();

    const int tx = tid & 15, ty = tid >> 4;
    float acc[4][4] = {};
    #pragma unroll
    for (int k = 0; k < 64; k++) {
        float a[4], w[4];
        #pragma unroll
        for (int i = 0; i < 4; i++) a[i] = Xs[(ty * 4 + i) * 65 + k];
        #pragma unroll
        for (int j = 0; j < 4; j++) w[j] = Ws[k * 64 + tx * 4 + j];
        #pragma unroll
        for (int i = 0; i < 4; i++)
            #pragma unroll
            for (int j = 0; j < 4; j++)
                acc[i][j] = fmaf(a[i], w[j], acc[i][j]);
    }

    #pragma unroll
    for (int i = 0; i < 4; i++) {
        int m = m0 + ty * 4 + i;
        #pragma unroll
        for (int j = 0; j < 4; j++) {
            int n = n0 + tx * 4 + j;
            float v = acc[i][j] + b1[n];
            v = (n < HH) ? tanhf(v) : sigmoidf_(v);
            g_buf[m * G3 + n] = v;
        }
    }
}

// ---------------------------------------------------------------------------
// fo-pool scan, 3 phases (affine chunked scan).
// Phase C writes the bf16 hi/lo split of o*c directly into Ahi/Alo.
// ---------------------------------------------------------------------------
__global__ __launch_bounds__(256) void scan_phaseA_kernel()
{
    const int ch = blockIdx.x * 256 + threadIdx.x;
    const int chunk = blockIdx.y;
    const int b = ch >> 9, h = ch & 511;
    const int t0 = chunk * CHUNK;
    float c = 0.0f, F = 1.0f;
    #pragma unroll
    for (int i = 0; i < CHUNK; i++) {
        int base = ((t0 + i) * BB + b) * G3 + h;
        float z = g_buf[base];
        float f = g_buf[base + HH];
        c = f * c + (1.0f - f) * z;
        F *= f;
    }
    F_buf[chunk * NCH + ch]  = F;
    Gc_buf[chunk * NCH + ch] = c;
}

__global__ __launch_bounds__(256) void scan_phaseB_kernel()
{
    const int ch = blockIdx.x * 256 + threadIdx.x;
    float c = 0.0f;
    #pragma unroll
    for (int j = 0; j < NCHUNK; j++) {
        c0_buf[j * NCH + ch] = c;
        float F = F_buf[j * NCH + ch];
        float G = Gc_buf[j * NCH + ch];
        c = F * c + G;
    }
}

__global__ __launch_bounds__(256) void scan_phaseC_kernel(int layer)
{
    const int ch = blockIdx.x * 256 + threadIdx.x;
    const int chunk = blockIdx.y;
    const int b = ch >> 9, h = ch & 511;
    const int t0 = chunk * CHUNK;
    float c = c0_buf[chunk * NCH + ch];
    #pragma unroll
    for (int i = 0; i < CHUNK; i++) {
        int t = t0 + i;
        int base = (t * BB + b) * G3 + h;
        float z = g_buf[base];
        float f = g_buf[base + HH];
        float o = g_buf[base + 2 * HH];
        c = f * c + (1.0f - f) * z;
        float val = o * c;
        int idx = (layer == 0) ? ((t * BB + b) * HH + h) : ((b * TT + t) * HH + h);
        __nv_bfloat16 hi = __float2bfloat16_rn(val);
        float r = val - __bfloat162float(hi);
        Ahi_buf[idx] = hi;
        Alo_buf[idx] = __float2bfloat16_rn(r);
    }
}

// ---------------------------------------------------------------------------
// W [K=512, N] row-major  ->  B [N, K=512] bf16 hi/lo (transpose + split)
// ---------------------------------------------------------------------------
__global__ __launch_bounds__(256) void transpose_split_kernel(
    const float* __restrict__ W, int N,
    __nv_bfloat16* __restrict__ Bhi, __nv_bfloat16* __restrict__ Blo)
{
    __shared__ float ts[32][33];
    const int n0 = blockIdx.x * 32;
    const int k0 = blockIdx.y * 32;
    const int tx = threadIdx.x, ty = threadIdx.y;

    #pragma unroll
    for (int i = 0; i < 4; i++)
        ts[ty + i * 8][tx] = W[(size_t)(k0 + ty + i * 8) * N + n0 + tx];
    __syncthreads();
    #pragma unroll
    for (int i = 0; i < 4; i++) {
        float x = ts[tx][ty + i * 8];
        __nv_bfloat16 h = __float2bfloat16_rn(x);
        float r = x - __bfloat162float(h);
        size_t o = (size_t)(n0 + ty + i * 8) * KK + k0 + tx;
        Bhi[o] = h;
        Blo[o] = __float2bfloat16_rn(r);
    }
}

// ---------------------------------------------------------------------------
// HMMA bf16 split GEMM, 3 passes FUSED per k-chunk:
// stage {Ahi, Alo, Bhi, Blo} 128x32 tiles once, run Ahi*Bhi + Ahi*Blo + Alo*Bhi
// reusing register fragments (Ahi and Bhi each feed 2 passes).
// CTA 128x128, 4 warps (2m x 2n), warp 64x64, mma m16n8k16.
// SMEM rows padded to 40 bf16 (80B): ldmatrix conflict-free.
// Double-buffered cp.async, 16 outer chunks, 1 barrier per chunk.
// ---------------------------------------------------------------------------
#define LDS_STRIDE 40          // bf16 elems per smem row (32 data + 8 pad)
#define TILE_BYTES 10240       // 128 rows * 80 B
#define STAGE_BYTES (4 * TILE_BYTES)   // Ahi, Alo, Bhi, Blo
#define TG_SMEM (2 * STAGE_BYTES)      // 81920

template<int NGLOB, int ACT>
__global__ __launch_bounds__(128, 2) void tgemm_kernel(
    const __nv_bfloat16* __restrict__ Ahi, const __nv_bfloat16* __restrict__ Alo,
    const __nv_bfloat16* __restrict__ Bhi, const __nv_bfloat16* __restrict__ Blo,
    const float* __restrict__ bias, float* __restrict__ C)
{
    extern __shared__ __nv_bfloat16 dsm[];
    const uint32_t sbase = smem_u32(dsm);

    const int tid  = threadIdx.x;
    const int wid  = tid >> 5;
    const int lane = tid & 31;
    const int m0 = blockIdx.y * 128;
    const int n0 = blockIdx.x * 128;
    const int wm = (wid & 1) * 64;
    const int wn = (wid >> 1) * 64;

    const int ldRow = tid >> 2;          // 0..31
    const int ldG   = tid & 3;           // 16B chunk within 64B row

    float acc[4][8][4] = {};

    auto issue_loads = [&](int kc, int s) {
        const int k0 = kc * 32;
        const uint32_t st = sbase + s * STAGE_BYTES;
        #pragma unroll
        for (int it = 0; it < 4; it++) {
            int row = ldRow + it * 32;
            uint32_t soff = (uint32_t)(row * LDS_STRIDE + ldG * 8) * 2;
            size_t ga = (size_t)(m0 + row) * KK + k0 + ldG * 8;
            size_t gb = (size_t)(n0 + row) * KK + k0 + ldG * 8;
            cp_async16(st + 0 * TILE_BYTES + soff, Ahi + ga);
            cp_async16(st + 1 * TILE_BYTES + soff, Alo + ga);
            cp_async16(st + 2 * TILE_BYTES + soff, Bhi + gb);
            cp_async16(st + 3 * TILE_BYTES + soff, Blo + gb);
        }
        cp_commit();
    };

    issue_loads(0, 0);

    for (int kc = 0; kc < 16; kc++) {
        const int s = kc & 1;
        cp_wait<0>();
        __syncthreads();
        if (kc + 1 < 16) issue_loads(kc + 1, s ^ 1);

        const uint32_t st = sbase + s * STAGE_BYTES;
        const uint32_t sAhi = st;
        const uint32_t sAlo = st + 1 * TILE_BYTES;
        const uint32_t sBhi = st + 2 * TILE_BYTES;
        const uint32_t sBlo = st + 3 * TILE_BYTES;

        #pragma unroll
        for (int ks = 0; ks < 2; ks++) {
            const int kb = ks * 32;
            const uint32_t aoff = (uint32_t)((wm + (lane & 15)) * LDS_STRIDE) * 2
                                  + kb + ((lane >> 4) * 16);
            const uint32_t boff = (uint32_t)((wn + (lane & 7) + ((lane >> 4) & 1) * 8)
                                  * LDS_STRIDE) * 2 + kb + (((lane >> 3) & 1) * 16);

            uint32_t af[4][4];
            uint32_t bhf[8][2];
            // --- pass 0: Ahi * Bhi ---
            #pragma unroll
            for (int mt = 0; mt < 4; mt++)
                ldm_x4(af[mt][0], af[mt][1], af[mt][2], af[mt][3],
                       sAhi + aoff + (uint32_t)(mt * 16 * LDS_STRIDE * 2));
            #pragma unroll
            for (int nt2 = 0; nt2 < 4; nt2++) {
                uint32_t r0, r1, r2, r3;
                ldm_x4(r0, r1, r2, r3, sBhi + boff + (uint32_t)(nt2 * 16 * LDS_STRIDE * 2));
                bhf[nt2 * 2 + 0][0] = r0; bhf[nt2 * 2 + 0][1] = r1;
                bhf[nt2 * 2 + 1][0] = r2; bhf[nt2 * 2 + 1][1] = r3;
            }
            #pragma unroll
            for (int mt = 0; mt < 4; mt++)
                #pragma unroll
                for (int nt = 0; nt < 8; nt++)
                    mma_bf16(acc[mt][nt][0], acc[mt][nt][1], acc[mt][nt][2], acc[mt][nt][3],
                             af[mt][0], af[mt][1], af[mt][2], af[mt][3],
                             bhf[nt][0], bhf[nt][1]);

            // --- pass 1: Ahi * Blo (Ahi frags still live) ---
            uint32_t blf[8][2];
            #pragma unroll
            for (int nt2 = 0; nt2 < 4; nt2++) {
                uint32_t r0, r1, r2, r3;
                ldm_x4(r0, r1, r2, r3, sBlo + boff + (uint32_t)(nt2 * 16 * LDS_STRIDE * 2));
                blf[nt2 * 2 + 0][0] = r0; blf[nt2 * 2 + 0][1] = r1;
                blf[nt2 * 2 + 1][0] = r2; blf[nt2 * 2 + 1][1] = r3;
            }
            #pragma unroll
            for (int mt = 0; mt < 4; mt++)
                #pragma unroll
                for (int nt = 0; nt < 8; nt++)
                    mma_bf16(acc[mt][nt][0], acc[mt][nt][1], acc[mt][nt][2], acc[mt][nt][3],
                             af[mt][0], af[mt][1], af[mt][2], af[mt][3],
                             blf[nt][0], blf[nt][1]);

            // --- pass 2: Alo * Bhi (overwrite af with Alo; Bhi frags still live) ---
            #pragma unroll
            for (int mt = 0; mt < 4; mt++)
                ldm_x4(af[mt][0], af[mt][1], af[mt][2], af[mt][3],
                       sAlo + aoff + (uint32_t)(mt * 16 * LDS_STRIDE * 2));
            #pragma unroll
            for (int mt = 0; mt < 4; mt++)
                #pragma unroll
                for (int nt = 0; nt < 8; nt++)
                    mma_bf16(acc[mt][nt][0], acc[mt][nt][1], acc[mt][nt][2], acc[mt][nt][3],
                             af[mt][0], af[mt][1], af[mt][2], af[mt][3],
                             bhf[nt][0], bhf[nt][1]);
        }
    }

    // Epilogue: bias (+ optional activation), float2 stores.
    const int g = lane >> 2;
    const int cpair = (lane & 3) * 2;
    #pragma unroll
    for (int nt = 0; nt < 8; nt++) {
        int n = n0 + wn + nt * 8 + cpair;
        float bv0 = __ldg(bias + n);
        float bv1 = __ldg(bias + n + 1);
        #pragma unroll
        for (int mt = 0; mt < 4; mt++) {
            #pragma unroll
            for (int half = 0; half < 2; half++) {
                int m = m0 + wm + mt * 16 + g + half * 8;
                float x0 = acc[mt][nt][half * 2 + 0] + bv0;
                float x1 = acc[mt][nt][half * 2 + 1] + bv1;
                if (ACT) {
                    x0 = (n < HH) ? tanhf(x0) : sigmoidf_(x0);
                    x1 = (n + 1 < HH) ? tanhf(x1) : sigmoidf_(x1);
                }
                float2 v = make_float2(x0, x1);
                *(float2*)(C + (size_t)m * NGLOB + n) = v;
            }
        }
    }
}

// ---------------------------------------------------------------------------
// Launch
// ---------------------------------------------------------------------------
extern "C" void kernel_launch(void* const* d_in, const int* in_sizes, int n_in,
                              void* d_out, int out_size)
{
    const int*   inputs = (const int*)d_in[0];
    const float* emb    = (const float*)d_in[1];
    const float* W1     = (const float*)d_in[2];
    const float* b1     = (const float*)d_in[3];
    const float* W2     = (const float*)d_in[4];
    const float* b2     = (const float*)d_in[5];
    const float* Wp     = (const float*)d_in[6];
    const float* bp     = (const float*)d_in[7];
    float* out = (float*)d_out;

    cudaFuncSetAttribute(tgemm_kernel<G3, 1>,
                         cudaFuncAttributeMaxDynamicSharedMemorySize, TG_SMEM);
    cudaFuncSetAttribute(tgemm_kernel<VV, 0>,
                         cudaFuncAttributeMaxDynamicSharedMemorySize, TG_SMEM);

    float* g_gbuf;
    __nv_bfloat16 *g_Ahi, *g_Alo, *g_B2hi, *g_B2lo, *g_Bphi, *g_Bplo;
    cudaGetSymbolAddress((void**)&g_gbuf, g_buf);
    cudaGetSymbolAddress((void**)&g_Ahi,  Ahi_buf);
    cudaGetSymbolAddress((void**)&g_Alo,  Alo_buf);
    cudaGetSymbolAddress((void**)&g_B2hi, B2hi_buf);
    cudaGetSymbolAddress((void**)&g_B2lo, B2lo_buf);
    cudaGetSymbolAddress((void**)&g_Bphi, Bphi_buf);
    cudaGetSymbolAddress((void**)&g_Bplo, Bplo_buf);

    // Weight prep (independent of activations)
    transpose_split_kernel<<<dim3(G3 / 32, KK / 32), dim3(32, 8)>>>(W2, G3, g_B2hi, g_B2lo);
    transpose_split_kernel<<<dim3(VV / 32, KK / 32), dim3(32, 8)>>>(Wp, VV, g_Bphi, g_Bplo);

    // Layer 1: embed + GEMM1 + activations -> g_buf
    gemm1_kernel<<<dim3(G3 / 64, MM / 64), 256>>>(inputs, emb, W1, b1);

    // Layer 1 fo-pool -> Ahi/Alo (bf16 split), rows t*B+b
    scan_phaseA_kernel<<<dim3(NCH / 256, NCHUNK), 256>>>();
    scan_phaseB_kernel<<<NCH / 256, 256>>>();
    scan_phaseC_kernel<<<dim3(NCH / 256, NCHUNK), 256>>>(0);

    // Layer 2: HMMA split-bf16 GEMM -> g_buf with activations
    tgemm_kernel<G3, 1><<<dim3(G3 / 128, MM / 128), 128, TG_SMEM>>>(
        g_Ahi, g_Alo, g_B2hi, g_B2lo, b2, g_gbuf);

    // Layer 2 fo-pool -> Ahi/Alo (bf16 split), rows b*T+t
    scan_phaseA_kernel<<<dim3(NCH / 256, NCHUNK), 256>>>();
    scan_phaseB_kernel<<<NCH / 256, 256>>>();
    scan_phaseC_kernel<<<dim3(NCH / 256, NCHUNK), 256>>>(1);

    // Projection: HMMA split-bf16 GEMM -> out
    tgemm_kernel<VV, 0><<<dim3(VV / 128, MM / 128), 128, TG_SMEM>>>(
        g_Ahi, g_Alo, g_Bphi, g_Bplo, bp, out);
}